// round 7
// baseline (speedup 1.0000x reference)
#include <cuda_runtime.h>
#include <cuda_bf16.h>
#include <cstdint>

// Problem constants
#define B_   4
#define N_   1024
#define D_   1024
#define H_   16
#define DH_  64
#define M_   (B_ * N_)    // 4096
#define BH_  (B_ * H_)    // 64

// Scratch (allocation-free rule: __device__ globals)
__device__ __nv_bfloat16 g_qh[(size_t)BH_ * N_ * DH_];
__device__ __nv_bfloat16 g_ql[(size_t)BH_ * N_ * DH_];
__device__ __nv_bfloat16 g_kh[(size_t)BH_ * N_ * DH_];
__device__ __nv_bfloat16 g_kl[(size_t)BH_ * N_ * DH_];
__device__ __nv_bfloat16 g_vh[(size_t)BH_ * N_ * DH_];
__device__ __nv_bfloat16 g_vl[(size_t)BH_ * N_ * DH_];
__device__ __nv_bfloat16 g_wh[(size_t)BH_ * N_ * N_];
__device__ __nv_bfloat16 g_wl[(size_t)BH_ * N_ * N_];
__device__ __nv_bfloat16 g_inh[3][(size_t)M_ * D_];
__device__ __nv_bfloat16 g_inl[3][(size_t)M_ * D_];
__device__ __nv_bfloat16 g_wth[4][(size_t)D_ * D_];
__device__ __nv_bfloat16 g_wtl[4][(size_t)D_ * D_];
__device__ __nv_bfloat16 g_ah[(size_t)M_ * D_];
__device__ __nv_bfloat16 g_al[(size_t)M_ * D_];
__device__ int   g_mask4;

// ===========================================================================
// Helpers (generic PTX, sm_80+ only)
// ===========================================================================
__device__ __forceinline__ uint32_t smem_u32(const void* p) {
    uint32_t a;
    asm("{ .reg .u64 t; cvta.to.shared.u64 t, %1; cvt.u32.u64 %0, t; }" : "=r"(a) : "l"(p));
    return a;
}
__device__ __forceinline__ void ldsm_x4(uint32_t* r, uint32_t addr) {
    asm volatile("ldmatrix.sync.aligned.m8n8.x4.shared.b16 {%0,%1,%2,%3}, [%4];"
                 : "=r"(r[0]), "=r"(r[1]), "=r"(r[2]), "=r"(r[3]) : "r"(addr));
}
__device__ __forceinline__ void ldsm_x4_t(uint32_t* r, uint32_t addr) {
    asm volatile("ldmatrix.sync.aligned.m8n8.x4.trans.shared.b16 {%0,%1,%2,%3}, [%4];"
                 : "=r"(r[0]), "=r"(r[1]), "=r"(r[2]), "=r"(r[3]) : "r"(addr));
}
__device__ __forceinline__ void mma_bf16(float* c, const uint32_t* a, const uint32_t* b) {
    asm volatile(
        "mma.sync.aligned.m16n8k16.row.col.f32.bf16.bf16.f32 "
        "{%0,%1,%2,%3}, {%4,%5,%6,%7}, {%8,%9}, {%0,%1,%2,%3};"
        : "+f"(c[0]), "+f"(c[1]), "+f"(c[2]), "+f"(c[3])
        : "r"(a[0]), "r"(a[1]), "r"(a[2]), "r"(a[3]), "r"(b[0]), "r"(b[1]));
}
__device__ __forceinline__ void cp16(uint32_t smem, const void* g) {
    asm volatile("cp.async.ca.shared.global [%0], [%1], 16;" :: "r"(smem), "l"(g));
}
__device__ __forceinline__ void cp_commit() { asm volatile("cp.async.commit_group;"); }
template <int N>
__device__ __forceinline__ void cp_wait() { asm volatile("cp.async.wait_group %0;" :: "n"(N)); }

// ===========================================================================
// One-time fp32 -> bf16 hi/lo conversion
// ===========================================================================
__global__ void cvt_hilo(const float* __restrict__ src,
                         __nv_bfloat16* __restrict__ dh,
                         __nv_bfloat16* __restrict__ dl, int n4) {
    const int i = blockIdx.x * blockDim.x + threadIdx.x;
    if (i >= n4) return;
    float4 v = ((const float4*)src)[i];
    __nv_bfloat16 h0 = __float2bfloat16(v.x), h1 = __float2bfloat16(v.y);
    __nv_bfloat16 h2 = __float2bfloat16(v.z), h3 = __float2bfloat16(v.w);
    __nv_bfloat16 l0 = __float2bfloat16(v.x - __bfloat162float(h0));
    __nv_bfloat16 l1 = __float2bfloat16(v.y - __bfloat162float(h1));
    __nv_bfloat16 l2 = __float2bfloat16(v.z - __bfloat162float(h2));
    __nv_bfloat16 l3 = __float2bfloat16(v.w - __bfloat162float(h3));
    ((__nv_bfloat162*)dh)[i * 2]     = __nv_bfloat162(h0, h1);
    ((__nv_bfloat162*)dh)[i * 2 + 1] = __nv_bfloat162(h2, h3);
    ((__nv_bfloat162*)dl)[i * 2]     = __nv_bfloat162(l0, l1);
    ((__nv_bfloat162*)dl)[i * 2 + 1] = __nv_bfloat162(l2, l3);
}

// ===========================================================================
// bf16x3 NT GEMM, bf16 hi/lo operands, cp.async staging. (unchanged from R6)
// ===========================================================================
#define BK_      32
#define LDS_     40
#define TILE_B   (128 * LDS_ * 2)
#define BUF_B    (4 * TILE_B)
#define NUM_KB   (D_ / BK_)

template <int MODE>
__global__ void __launch_bounds__(256, 1) gemm_mma(const __nv_bfloat16* __restrict__ Ah,
                                                   const __nv_bfloat16* __restrict__ Al,
                                                   const __nv_bfloat16* __restrict__ Bh,
                                                   const __nv_bfloat16* __restrict__ Bl,
                                                   const float* __restrict__ bias,
                                                   float* __restrict__ C,
                                                   __nv_bfloat16* __restrict__ Chi,
                                                   __nv_bfloat16* __restrict__ Clo) {
    extern __shared__ char smem[];
    __shared__ float s_bias[128];

    const int tid = threadIdx.x;
    const int wid = tid >> 5;
    const int lane = tid & 31;
    const int warp_m = wid >> 2;
    const int warp_n = wid & 3;
    const int row0 = blockIdx.y * 128;
    const int col0 = blockIdx.x * 128;

    if (tid < 128) s_bias[tid] = bias[col0 + tid];

    const int r  = tid >> 1;
    const int half = tid & 1;
    const __nv_bfloat16* Ah_p = Ah + (size_t)(row0 + r) * D_ + half * 16;
    const __nv_bfloat16* Al_p = Al + (size_t)(row0 + r) * D_ + half * 16;
    const __nv_bfloat16* Bh_p = Bh + (size_t)(col0 + r) * D_ + half * 16;
    const __nv_bfloat16* Bl_p = Bl + (size_t)(col0 + r) * D_ + half * 16;
    const uint32_t sb = smem_u32(smem);
    const uint32_t st = sb + (uint32_t)r * (LDS_ * 2) + (uint32_t)half * 32;

    const int seg = lane >> 3, l7 = lane & 7;
    const int a_row = warp_m * 64 + (seg & 1) * 8 + l7;
    const int a_colb = (((seg >> 1) & 1) * 8) * 2;
    const int b_row = warp_n * 32 + ((seg >> 1) & 1) * 8 + l7;
    const int b_colb = ((seg & 1) * 8) * 2;

    float acc[4][4][4] = {};

    {
        cp16(st + 0*TILE_B,      Ah_p);
        cp16(st + 0*TILE_B + 16, Ah_p + 8);
        cp16(st + 1*TILE_B,      Al_p);
        cp16(st + 1*TILE_B + 16, Al_p + 8);
        cp16(st + 2*TILE_B,      Bh_p);
        cp16(st + 2*TILE_B + 16, Bh_p + 8);
        cp16(st + 3*TILE_B,      Bl_p);
        cp16(st + 3*TILE_B + 16, Bl_p + 8);
        cp_commit();
    }

    for (int kb = 0; kb < NUM_KB; kb++) {
        if (kb + 1 < NUM_KB) {
            const int k0 = (kb + 1) * BK_;
            const uint32_t nst = st + (uint32_t)((kb + 1) & 1) * BUF_B;
            cp16(nst + 0*TILE_B,      Ah_p + k0);
            cp16(nst + 0*TILE_B + 16, Ah_p + k0 + 8);
            cp16(nst + 1*TILE_B,      Al_p + k0);
            cp16(nst + 1*TILE_B + 16, Al_p + k0 + 8);
            cp16(nst + 2*TILE_B,      Bh_p + k0);
            cp16(nst + 2*TILE_B + 16, Bh_p + k0 + 8);
            cp16(nst + 3*TILE_B,      Bl_p + k0);
            cp16(nst + 3*TILE_B + 16, Bl_p + k0 + 8);
            cp_commit();
            cp_wait<1>();
        } else {
            cp_wait<0>();
        }
        __syncthreads();

        const uint32_t buf = sb + (uint32_t)(kb & 1) * BUF_B;
#pragma unroll
        for (int s = 0; s < 2; s++) {
            uint32_t a_hi[4][4], a_lo[4][4], b_hi[4][2], b_lo[4][2];
#pragma unroll
            for (int mt = 0; mt < 4; mt++) {
                const uint32_t off = (uint32_t)(a_row + mt * 16) * (LDS_ * 2) + a_colb + s * 32;
                ldsm_x4(a_hi[mt], buf + 0 * TILE_B + off);
                ldsm_x4(a_lo[mt], buf + 1 * TILE_B + off);
            }
#pragma unroll
            for (int p = 0; p < 2; p++) {
                const uint32_t off = (uint32_t)(b_row + p * 16) * (LDS_ * 2) + b_colb + s * 32;
                uint32_t th[4], tl[4];
                ldsm_x4(th, buf + 2 * TILE_B + off);
                ldsm_x4(tl, buf + 3 * TILE_B + off);
                b_hi[2*p][0] = th[0]; b_hi[2*p][1] = th[1];
                b_hi[2*p+1][0] = th[2]; b_hi[2*p+1][1] = th[3];
                b_lo[2*p][0] = tl[0]; b_lo[2*p][1] = tl[1];
                b_lo[2*p+1][0] = tl[2]; b_lo[2*p+1][1] = tl[3];
            }
#pragma unroll
            for (int mt = 0; mt < 4; mt++)
#pragma unroll
                for (int nt = 0; nt < 4; nt++) {
                    mma_bf16(acc[mt][nt], a_hi[mt], b_hi[nt]);
                    mma_bf16(acc[mt][nt], a_lo[mt], b_hi[nt]);
                    mma_bf16(acc[mt][nt], a_hi[mt], b_lo[nt]);
                }
        }
        __syncthreads();
    }

    const int group = lane >> 2, tg = lane & 3;
#pragma unroll
    for (int mt = 0; mt < 4; mt++) {
#pragma unroll
        for (int nt = 0; nt < 4; nt++) {
#pragma unroll
            for (int rp = 0; rp < 2; rp++) {
                const int row = row0 + warp_m * 64 + mt * 16 + group + rp * 8;
                const int lcol = warp_n * 32 + nt * 8 + tg * 2;
                const float v0 = acc[mt][nt][rp * 2 + 0] + s_bias[lcol];
                const float v1 = acc[mt][nt][rp * 2 + 1] + s_bias[lcol + 1];
                if (MODE == 0) {
                    C[(size_t)row * D_ + col0 + lcol] = v0;
                    C[(size_t)row * D_ + col0 + lcol + 1] = v1;
                } else {
                    const int b = row >> 10;
                    const int n = row & (N_ - 1);
                    const int col = col0 + lcol;
                    const int h = col >> 6;
                    const int dh = col & (DH_ - 1);
                    const size_t idx = (((size_t)b * H_ + h) * N_ + n) * DH_ + dh;
                    __nv_bfloat16 h0 = __float2bfloat16(v0);
                    __nv_bfloat16 h1 = __float2bfloat16(v1);
                    __nv_bfloat16 l0 = __float2bfloat16(v0 - __bfloat162float(h0));
                    __nv_bfloat16 l1 = __float2bfloat16(v1 - __bfloat162float(h1));
                    *(__nv_bfloat162*)(Chi + idx) = __nv_bfloat162(h0, h1);
                    *(__nv_bfloat162*)(Clo + idx) = __nv_bfloat162(l0, l1);
                }
            }
        }
    }
}

// ===========================================================================
// Mask dtype detection (unchanged)
// ===========================================================================
__global__ void detect_mask_kind(const unsigned char* __restrict__ m) {
    __shared__ int has_gt1, has_mis;
    if (threadIdx.x == 0) { has_gt1 = 0; has_mis = 0; }
    __syncthreads();
    int lg = 0, lm = 0;
    for (int i = threadIdx.x * 16; i < 65536; i += blockDim.x * 16) {
        uint4 v = *(const uint4*)(m + i);
        unsigned int w[4] = {v.x, v.y, v.z, v.w};
#pragma unroll
        for (int j = 0; j < 4; j++) {
#pragma unroll
            for (int b = 0; b < 4; b++) {
                unsigned int byte = (w[j] >> (8 * b)) & 0xFFu;
                int pos = i + j * 4 + b;
                if (byte > 1u) lg = 1;
                if (byte != 0u && (pos & 3)) lm = 1;
            }
        }
    }
    if (lg) atomicOr(&has_gt1, 1);
    if (lm) atomicOr(&has_mis, 1);
    __syncthreads();
    if (threadIdx.x == 0) g_mask4 = (has_gt1 || !has_mis) ? 1 : 0;
}

// ===========================================================================
// FUSED scores + mask + softmax.
// CTA = 16 rows x 1024 cols of one (b,h). Scores live in registers
// (64 fp32/thread over 2 col-passes of 512). k hi/lo staged in smem per pass.
// Emits normalized weights: fp32 (output) + bf16 hi/lo (for attn GEMM).
// ===========================================================================
#define FR_    16
#define LDKB   144                          // padded row bytes (72 bf16)
#define FS_QH  0
#define FS_QL  (FR_ * LDKB)                 // 2304
#define FS_KH  (2 * FR_ * LDKB)             // 4608
#define FS_KL  (FS_KH + 512 * LDKB)         // 78336
#define FS_TOT (FS_KL + 512 * LDKB)         // 152064

__global__ void __launch_bounds__(256, 1) fused_scores_softmax(
        const unsigned char* __restrict__ maskp, float* __restrict__ wout) {
    extern __shared__ char smem[];
    __shared__ float s_red[2][FR_][8];
    const int tid = threadIdx.x;
    const int w = tid >> 5;
    const int lane = tid & 31;
    const int bh = blockIdx.y;
    const int row0 = blockIdx.x * FR_;

    // load q strip (16 rows, hi+lo): 128 chunks each
    {
        const int ci = tid & 127;
        const int row = ci >> 3, c = ci & 7;
        const size_t src = ((size_t)bh * N_ + row0 + row) * DH_ + c * 8;
        if (tid < 128)
            *(uint4*)(smem + FS_QH + row * LDKB + c * 16) = *(const uint4*)(g_qh + src);
        else
            *(uint4*)(smem + FS_QL + row * LDKB + c * 16) = *(const uint4*)(g_ql + src);
    }

    const uint32_t sb = smem_u32(smem);
    const int seg = lane >> 3, l7 = lane & 7;
    const uint32_t a_off0 = (uint32_t)((seg & 1) * 8 + l7) * LDKB + ((seg >> 1) & 1) * 16;
    const int b_row_base = w * 64 + ((seg >> 1) & 1) * 8 + l7;
    const uint32_t b_colb = (seg & 1) * 16;

    float acc[2][8][4] = {};

#pragma unroll
    for (int pass = 0; pass < 2; pass++) {
        __syncthreads();   // q ready (pass 0) / previous pass k consumers done
        // load k tile rows [pass*512, +512), hi+lo
#pragma unroll 4
        for (int j = 0; j < 16; j++) {
            const int ci = j * 256 + tid;
            const int row = ci >> 3, c = ci & 7;
            const size_t src = ((size_t)bh * N_ + pass * 512 + row) * DH_ + c * 8;
            *(uint4*)(smem + FS_KH + row * LDKB + c * 16) = *(const uint4*)(g_kh + src);
            *(uint4*)(smem + FS_KL + row * LDKB + c * 16) = *(const uint4*)(g_kl + src);
        }
        __syncthreads();

#pragma unroll
        for (int s = 0; s < 4; s++) {
            uint32_t a_hi[4], a_lo[4];
            ldsm_x4(a_hi, sb + FS_QH + a_off0 + s * 32);
            ldsm_x4(a_lo, sb + FS_QL + a_off0 + s * 32);
#pragma unroll
            for (int p = 0; p < 4; p++) {
                const uint32_t off = (uint32_t)(b_row_base + p * 16) * LDKB + b_colb + s * 32;
                uint32_t th[4], tl[4];
                ldsm_x4(th, sb + FS_KH + off);
                ldsm_x4(tl, sb + FS_KL + off);
                uint32_t b0h[2] = {th[0], th[1]}, b1h[2] = {th[2], th[3]};
                uint32_t b0l[2] = {tl[0], tl[1]}, b1l[2] = {tl[2], tl[3]};
                mma_bf16(acc[pass][2*p],   a_hi, b0h);
                mma_bf16(acc[pass][2*p+1], a_hi, b1h);
                mma_bf16(acc[pass][2*p],   a_lo, b0h);
                mma_bf16(acc[pass][2*p+1], a_lo, b1h);
                mma_bf16(acc[pass][2*p],   a_hi, b0l);
                mma_bf16(acc[pass][2*p+1], a_hi, b1l);
            }
        }
    }

    const int group = lane >> 2, tg = lane & 3;
    const int m4 = g_mask4;
    const unsigned int* mask32 = (const unsigned int*)maskp;

    // scale + mask (in registers)
#pragma unroll
    for (int pass = 0; pass < 2; pass++)
#pragma unroll
        for (int nt = 0; nt < 8; nt++)
#pragma unroll
            for (int rg = 0; rg < 4; rg++) {
                const int row = row0 + group + (rg >> 1) * 8;
                const int col = pass * 512 + w * 64 + nt * 8 + tg * 2 + (rg & 1);
                const size_t idx = ((size_t)bh * N_ + row) * N_ + col;
                const bool masked = m4 ? (mask32[idx] != 0u) : (maskp[idx] != 0);
                acc[pass][nt][rg] = masked ? -1e10f : acc[pass][nt][rg] * 0.125f;
            }

    // row max (rows: group, group+8)
    float mx[2] = {-3.4e38f, -3.4e38f};
#pragma unroll
    for (int pass = 0; pass < 2; pass++)
#pragma unroll
        for (int nt = 0; nt < 8; nt++) {
            mx[0] = fmaxf(mx[0], fmaxf(acc[pass][nt][0], acc[pass][nt][1]));
            mx[1] = fmaxf(mx[1], fmaxf(acc[pass][nt][2], acc[pass][nt][3]));
        }
#pragma unroll
    for (int o = 1; o <= 2; o <<= 1) {
        mx[0] = fmaxf(mx[0], __shfl_xor_sync(~0u, mx[0], o));
        mx[1] = fmaxf(mx[1], __shfl_xor_sync(~0u, mx[1], o));
    }
    if (tg == 0) { s_red[0][group][w] = mx[0]; s_red[0][group + 8][w] = mx[1]; }
    __syncthreads();
    float rmax[2];
#pragma unroll
    for (int hf = 0; hf < 2; hf++) {
        float t = s_red[0][group + hf * 8][0];
#pragma unroll
        for (int j = 1; j < 8; j++) t = fmaxf(t, s_red[0][group + hf * 8][j]);
        rmax[hf] = t;
    }

    // exp + row sum
    float sm[2] = {0.0f, 0.0f};
#pragma unroll
    for (int pass = 0; pass < 2; pass++)
#pragma unroll
        for (int nt = 0; nt < 8; nt++)
#pragma unroll
            for (int rg = 0; rg < 4; rg++) {
                const float e = __expf(acc[pass][nt][rg] - rmax[rg >> 1]);
                acc[pass][nt][rg] = e;
                sm[rg >> 1] += e;
            }
#pragma unroll
    for (int o = 1; o <= 2; o <<= 1) {
        sm[0] += __shfl_xor_sync(~0u, sm[0], o);
        sm[1] += __shfl_xor_sync(~0u, sm[1], o);
    }
    if (tg == 0) { s_red[1][group][w] = sm[0]; s_red[1][group + 8][w] = sm[1]; }
    __syncthreads();
    float inv[2];
#pragma unroll
    for (int hf = 0; hf < 2; hf++) {
        float t = 0.0f;
#pragma unroll
        for (int j = 0; j < 8; j++) t += s_red[1][group + hf * 8][j];
        inv[hf] = 1.0f / t;
    }

    // write normalized weights: fp32 + bf16 hi/lo
#pragma unroll
    for (int pass = 0; pass < 2; pass++)
#pragma unroll
        for (int nt = 0; nt < 8; nt++)
#pragma unroll
            for (int hf = 0; hf < 2; hf++) {
                const int row = row0 + group + hf * 8;
                const int col = pass * 512 + w * 64 + nt * 8 + tg * 2;
                const float v0 = acc[pass][nt][hf * 2 + 0] * inv[hf];
                const float v1 = acc[pass][nt][hf * 2 + 1] * inv[hf];
                const size_t idx = ((size_t)bh * N_ + row) * N_ + col;
                *(float2*)(wout + idx) = make_float2(v0, v1);
                __nv_bfloat16 h0 = __float2bfloat16(v0);
                __nv_bfloat16 h1 = __float2bfloat16(v1);
                __nv_bfloat16 l0 = __float2bfloat16(v0 - __bfloat162float(h0));
                __nv_bfloat16 l1 = __float2bfloat16(v1 - __bfloat162float(h1));
                *(__nv_bfloat162*)(g_wh + idx) = __nv_bfloat162(h0, h1);
                *(__nv_bfloat162*)(g_wl + idx) = __nv_bfloat162(l0, l1);
            }
}

// ===========================================================================
// attn = weights @ v via mma, bf16x3; emits bf16 hi/lo [b,n,d]. (unchanged)
// ===========================================================================
#define LDQ    72
#define AT_B   (128 * LDQ * 2)
#define VT_B   (64 * LDQ * 2)
#define AB_B   (2 * AT_B + 2 * VT_B)
#define NKB_A  (N_ / 64)

__global__ void __launch_bounds__(256, 1) attn_mma(void) {
    extern __shared__ char smem[];
    const int tid = threadIdx.x;
    const int wid = tid >> 5;
    const int lane = tid & 31;
    const int warp_m = wid >> 1;
    const int warp_n = wid & 1;
    const int bh = blockIdx.y;
    const int row0 = blockIdx.x * 128;

    const __nv_bfloat16* whb = g_wh + (size_t)bh * N_ * N_;
    const __nv_bfloat16* wlb = g_wl + (size_t)bh * N_ * N_;
    const __nv_bfloat16* vhb = g_vh + (size_t)bh * N_ * DH_;
    const __nv_bfloat16* vlb = g_vl + (size_t)bh * N_ * DH_;

    const int ar = tid >> 1, ahalf = tid & 1;
    const uint32_t a_dst = (uint32_t)ar * (LDQ * 2) + (uint32_t)ahalf * 64;
    const int vr = tid >> 2, vq = tid & 3;
    const uint32_t v_dst = (uint32_t)vr * (LDQ * 2) + (uint32_t)vq * 32;

    {
        const size_t asrc = (size_t)(row0 + ar) * N_ + ahalf * 32;
        const size_t vsrc = (size_t)vr * DH_ + vq * 16;
#pragma unroll
        for (int j = 0; j < 4; j++) {
            *(uint4*)(smem + 0*AT_B + a_dst + j*16) = *(const uint4*)(whb + asrc + j*8);
            *(uint4*)(smem + 1*AT_B + a_dst + j*16) = *(const uint4*)(wlb + asrc + j*8);
        }
#pragma unroll
        for (int j = 0; j < 2; j++) {
            *(uint4*)(smem + 2*AT_B + 0*VT_B + v_dst + j*16) = *(const uint4*)(vhb + vsrc + j*8);
            *(uint4*)(smem + 2*AT_B + 1*VT_B + v_dst + j*16) = *(const uint4*)(vlb + vsrc + j*8);
        }
    }
    __syncthreads();

    const uint32_t sb = smem_u32(smem);
    const int l15 = lane & 15;
    const int a_row = warp_m * 32 + l15;
    const int a_colb = (lane >> 4) * 16;
    const int v_row = l15;
    const int v_colb = (warp_n * 32) * 2 + (lane >> 4) * 16;

    float acc[2][4][4] = {};
    uint4 pa[8], pv[4];

    for (int kb = 0; kb < NKB_A; kb++) {
        if (kb + 1 < NKB_A) {
            const int k0 = (kb + 1) * 64;
            const size_t asrc = (size_t)(row0 + ar) * N_ + k0 + ahalf * 32;
            const size_t vsrc = (size_t)(k0 + vr) * DH_ + vq * 16;
#pragma unroll
            for (int j = 0; j < 4; j++) {
                pa[j]     = *(const uint4*)(whb + asrc + j*8);
                pa[4 + j] = *(const uint4*)(wlb + asrc + j*8);
            }
#pragma unroll
            for (int j = 0; j < 2; j++) {
                pv[j]     = *(const uint4*)(vhb + vsrc + j*8);
                pv[2 + j] = *(const uint4*)(vlb + vsrc + j*8);
            }
        }

        const uint32_t buf = sb + (uint32_t)(kb & 1) * AB_B;
#pragma unroll
        for (int s = 0; s < 4; s++) {
            uint32_t a_hi[2][4], a_lo[2][4], b_hi[4][2], b_lo[4][2];
#pragma unroll
            for (int mt = 0; mt < 2; mt++) {
                const uint32_t off = (uint32_t)(a_row + mt * 16) * (LDQ * 2) + a_colb + s * 32;
                ldsm_x4(a_hi[mt], buf + 0 * AT_B + off);
                ldsm_x4(a_lo[mt], buf + 1 * AT_B + off);
            }
#pragma unroll
            for (int p = 0; p < 2; p++) {
                const uint32_t off = (uint32_t)(s * 16 + v_row) * (LDQ * 2) + v_colb + p * 32;
                uint32_t th[4], tl[4];
                ldsm_x4_t(th, buf + 2 * AT_B + 0 * VT_B + off);
                ldsm_x4_t(tl, buf + 2 * AT_B + 1 * VT_B + off);
                b_hi[2*p][0] = th[0]; b_hi[2*p][1] = th[1];
                b_hi[2*p+1][0] = th[2]; b_hi[2*p+1][1] = th[3];
                b_lo[2*p][0] = tl[0]; b_lo[2*p][1] = tl[1];
                b_lo[2*p+1][0] = tl[2]; b_lo[2*p+1][1] = tl[3];
            }
#pragma unroll
            for (int mt = 0; mt < 2; mt++)
#pragma unroll
                for (int nt = 0; nt < 4; nt++) {
                    mma_bf16(acc[mt][nt], a_hi[mt], b_hi[nt]);
                    mma_bf16(acc[mt][nt], a_lo[mt], b_hi[nt]);
                    mma_bf16(acc[mt][nt], a_hi[mt], b_lo[nt]);
                }
        }

        if (kb + 1 < NKB_A) {
            char* base = smem + ((kb + 1) & 1) * AB_B;
#pragma unroll
            for (int j = 0; j < 4; j++) {
                *(uint4*)(base + 0*AT_B + a_dst + j*16) = pa[j];
                *(uint4*)(base + 1*AT_B + a_dst + j*16) = pa[4 + j];
            }
#pragma unroll
            for (int j = 0; j < 2; j++) {
                *(uint4*)(base + 2*AT_B + 0*VT_B + v_dst + j*16) = pv[j];
                *(uint4*)(base + 2*AT_B + 1*VT_B + v_dst + j*16) = pv[2 + j];
            }
        }
        __syncthreads();
    }

    const int b = bh >> 4;
    const int h = bh & (H_ - 1);
    const int group = lane >> 2, tg = lane & 3;
#pragma unroll
    for (int mt = 0; mt < 2; mt++)
#pragma unroll
        for (int nt = 0; nt < 4; nt++)
#pragma unroll
            for (int rp = 0; rp < 2; rp++) {
                const int n = row0 + warp_m * 32 + mt * 16 + group + rp * 8;
                const int dh = warp_n * 32 + nt * 8 + tg * 2;
                const float v0 = acc[mt][nt][rp * 2 + 0];
                const float v1 = acc[mt][nt][rp * 2 + 1];
                const size_t idx = ((size_t)b * N_ + n) * D_ + h * DH_ + dh;
                __nv_bfloat16 h0 = __float2bfloat16(v0);
                __nv_bfloat16 h1 = __float2bfloat16(v1);
                __nv_bfloat16 l0 = __float2bfloat16(v0 - __bfloat162float(h0));
                __nv_bfloat16 l1 = __float2bfloat16(v1 - __bfloat162float(h1));
                *(__nv_bfloat162*)(g_ah + idx) = __nv_bfloat162(h0, h1);
                *(__nv_bfloat162*)(g_al + idx) = __nv_bfloat162(l0, l1);
            }
}

// ===========================================================================
extern "C" void kernel_launch(void* const* d_in, const int* in_sizes, int n_in,
                              void* d_out, int out_size) {
    const float* Q  = (const float*)d_in[0];
    const float* K  = (const float*)d_in[1];
    const float* V  = (const float*)d_in[2];
    const unsigned char* mask = (const unsigned char*)d_in[3];
    const float* Wq = (const float*)d_in[4];
    const float* bq = (const float*)d_in[5];
    const float* Wk = (const float*)d_in[6];
    const float* bk = (const float*)d_in[7];
    const float* Wv = (const float*)d_in[8];
    const float* bv = (const float*)d_in[9];
    const float* Wo = (const float*)d_in[10];
    const float* bo = (const float*)d_in[11];

    float* xout = (float*)d_out;
    float* wout = xout + (size_t)M_ * D_;

    __nv_bfloat16 *qh, *ql, *kh, *kl, *vh, *vl, *inh, *inl, *wth, *wtl, *ah, *al;
    cudaGetSymbolAddress((void**)&qh, g_qh);
    cudaGetSymbolAddress((void**)&ql, g_ql);
    cudaGetSymbolAddress((void**)&kh, g_kh);
    cudaGetSymbolAddress((void**)&kl, g_kl);
    cudaGetSymbolAddress((void**)&vh, g_vh);
    cudaGetSymbolAddress((void**)&vl, g_vl);
    cudaGetSymbolAddress((void**)&inh, g_inh);
    cudaGetSymbolAddress((void**)&inl, g_inl);
    cudaGetSymbolAddress((void**)&wth, g_wth);
    cudaGetSymbolAddress((void**)&wtl, g_wtl);
    cudaGetSymbolAddress((void**)&ah, g_ah);
    cudaGetSymbolAddress((void**)&al, g_al);

    const int gemm_smem = 2 * BUF_B;
    const int fs_smem = FS_TOT;
    const int attn_smem = 2 * AB_B;
    cudaFuncSetAttribute(gemm_mma<0>, cudaFuncAttributeMaxDynamicSharedMemorySize, gemm_smem);
    cudaFuncSetAttribute(gemm_mma<1>, cudaFuncAttributeMaxDynamicSharedMemorySize, gemm_smem);
    cudaFuncSetAttribute(fused_scores_softmax, cudaFuncAttributeMaxDynamicSharedMemorySize, fs_smem);
    cudaFuncSetAttribute(attn_mma, cudaFuncAttributeMaxDynamicSharedMemorySize, attn_smem);

    detect_mask_kind<<<1, 256>>>(mask);

    const size_t inN = (size_t)M_ * D_;
    const size_t wN  = (size_t)D_ * D_;
    cvt_hilo<<<(int)(inN / 4 / 256), 256>>>(Q, inh + 0 * inN, inl + 0 * inN, (int)(inN / 4));
    cvt_hilo<<<(int)(inN / 4 / 256), 256>>>(K, inh + 1 * inN, inl + 1 * inN, (int)(inN / 4));
    cvt_hilo<<<(int)(inN / 4 / 256), 256>>>(V, inh + 2 * inN, inl + 2 * inN, (int)(inN / 4));
    cvt_hilo<<<(int)(wN / 4 / 256), 256>>>(Wq, wth + 0 * wN, wtl + 0 * wN, (int)(wN / 4));
    cvt_hilo<<<(int)(wN / 4 / 256), 256>>>(Wk, wth + 1 * wN, wtl + 1 * wN, (int)(wN / 4));
    cvt_hilo<<<(int)(wN / 4 / 256), 256>>>(Wv, wth + 2 * wN, wtl + 2 * wN, (int)(wN / 4));
    cvt_hilo<<<(int)(wN / 4 / 256), 256>>>(Wo, wth + 3 * wN, wtl + 3 * wN, (int)(wN / 4));

    dim3 gp(D_ / 128, M_ / 128);
    gemm_mma<1><<<gp, 256, gemm_smem>>>(inh + 0*inN, inl + 0*inN, wth + 0*wN, wtl + 0*wN, bq, nullptr, qh, ql);
    gemm_mma<1><<<gp, 256, gemm_smem>>>(inh + 1*inN, inl + 1*inN, wth + 1*wN, wtl + 1*wN, bk, nullptr, kh, kl);
    gemm_mma<1><<<gp, 256, gemm_smem>>>(inh + 2*inN, inl + 2*inN, wth + 2*wN, wtl + 2*wN, bv, nullptr, vh, vl);

    fused_scores_softmax<<<dim3(N_ / FR_, BH_), 256, fs_smem>>>(mask, wout);
    attn_mma<<<dim3(N_ / 128, BH_), 256, attn_smem>>>();

    gemm_mma<0><<<gp, 256, gemm_smem>>>(ah, al, wth + 3*wN, wtl + 3*wN, bo, xout, nullptr, nullptr);
}